// round 5
// baseline (speedup 1.0000x reference)
#include <cuda_runtime.h>
#include <cuda_bf16.h>
#include <math.h>
#include <stdint.h>

// ---------------- problem constants ----------------
#define B_      64
#define EVI_    5
#define SEQS_   (B_ * EVI_)          // 320
#define L_      256
#define D_      768
#define WORDS_  32
#define TPW_    4
#define NN_     (SEQS_ * WORDS_)     // 10240 nodes
#define EE_     (NN_ * 16)           // 163840 edges
#define R_      4
#define DOUT_   768
#define LH_     1024
#define NC_     3
#define KTOT_   (5 * D_)             // 3840 fused K
#define NR_     (NN_ * R_)           // 40960 segments

// ---------------- scratch (device globals; no allocs allowed) ----------------
__device__ float g_x   [(size_t)NN_ * D_];          // x0 / x2
__device__ float g_acc [(size_t)NN_ * D_];          // x1
__device__ float g_h   [(size_t)R_ * NN_ * D_];     // per-relation aggregation
__device__ __nv_bfloat16 g_ahi[(size_t)NN_ * KTOT_];   // 78.6 MB
__device__ __nv_bfloat16 g_alo[(size_t)NN_ * KTOT_];
__device__ __nv_bfloat16 g_whi[(size_t)KTOT_ * D_];    // [k][n] 5.9 MB
__device__ __nv_bfloat16 g_wlo[(size_t)KTOT_ * D_];
__device__ int   g_cnt [NR_];
__device__ int   g_off [NR_ + 1];
__device__ int   g_cur [NR_];
__device__ int   g_elist[EE_];
__device__ float g_ev  [SEQS_ * 2 * DOUT_];
__device__ float g_attin[SEQS_ * (D_ + 2 * DOUT_)];
__device__ float g_hatt[SEQS_ * DOUT_];
__device__ float g_p   [SEQS_];
__device__ float g_a   [SEQS_];
__device__ float g_rep [B_ * (2 * DOUT_ + D_)];
__device__ float g_hid [B_ * LH_];

// ---------------- small device helpers ----------------
__device__ __forceinline__ uint32_t smem_u32(const void* p) {
    uint32_t a;
    asm("{ .reg .u64 t; cvta.to.shared.u64 t, %1; cvt.u32.u64 %0, t; }" : "=r"(a) : "l"(p));
    return a;
}
__device__ __forceinline__ uint32_t pack2(float lo, float hi) {
    uint32_t r;
    asm("cvt.rn.bf16x2.f32 %0, %1, %2;" : "=r"(r) : "f"(hi), "f"(lo));
    return r;
}
__device__ __forceinline__ void mma16816(float* c, const uint32_t* a, const uint32_t* b) {
    asm volatile("mma.sync.aligned.m16n8k16.row.col.f32.bf16.bf16.f32 "
                 "{%0,%1,%2,%3}, {%4,%5,%6,%7}, {%8,%9}, {%0,%1,%2,%3};"
                 : "+f"(c[0]), "+f"(c[1]), "+f"(c[2]), "+f"(c[3])
                 : "r"(a[0]), "r"(a[1]), "r"(a[2]), "r"(a[3]), "r"(b[0]), "r"(b[1]));
}
__device__ __forceinline__ void ldmx4(uint32_t* r, uint32_t addr) {
    asm volatile("ldmatrix.sync.aligned.m8n8.x4.shared.b16 {%0,%1,%2,%3}, [%4];"
                 : "=r"(r[0]), "=r"(r[1]), "=r"(r[2]), "=r"(r[3]) : "r"(addr));
}
__device__ __forceinline__ void ldmx4t(uint32_t* r, uint32_t addr) {
    asm volatile("ldmatrix.sync.aligned.m8n8.x4.trans.shared.b16 {%0,%1,%2,%3}, [%4];"
                 : "=r"(r[0]), "=r"(r[1]), "=r"(r[2]), "=r"(r[3]) : "r"(addr));
}
__device__ __forceinline__ void cp16(uint32_t dst, const void* src) {
    asm volatile("cp.async.cg.shared.global [%0], [%1], 16;" :: "r"(dst), "l"(src));
}

// ---------------- utility kernels ----------------
__global__ void zero4_kernel(float4* p, long long n4) {
    long long t = (long long)blockIdx.x * blockDim.x + threadIdx.x;
    if (t < n4) p[t] = make_float4(0.f, 0.f, 0.f, 0.f);
}
__global__ void relu_kernel(float* p, long long n) {
    long long t = (long long)blockIdx.x * blockDim.x + threadIdx.x;
    if (t < n) p[t] = fmaxf(p[t], 0.f);
}
__global__ void init_bias_kernel(float* C, const float* __restrict__ bias, long long M, int N) {
    long long t = (long long)blockIdx.x * blockDim.x + threadIdx.x;
    if (t < M * N) C[t] = bias[t % N];
}

// ---------------- graph prep: counts -> scan -> scatter (CSR) ----------------
__global__ void count_kernel(const int* __restrict__ eidx, const int* __restrict__ etype) {
    int e = blockIdx.x * blockDim.x + threadIdx.x;
    if (e >= EE_) return;
    atomicAdd(&g_cnt[eidx[EE_ + e] * R_ + etype[e]], 1);
}
__global__ void scan_kernel() {
    __shared__ int part[1024];
    int tid = threadIdx.x;
    int base = tid * 40;
    int s = 0;
#pragma unroll 8
    for (int i = 0; i < 40; ++i) s += g_cnt[base + i];
    part[tid] = s;
    __syncthreads();
    for (int o = 1; o < 1024; o <<= 1) {
        int v = (tid >= o) ? part[tid - o] : 0;
        __syncthreads();
        part[tid] += v;
        __syncthreads();
    }
    int run = tid ? part[tid - 1] : 0;
#pragma unroll 8
    for (int i = 0; i < 40; ++i) {
        int c = g_cnt[base + i];
        g_off[base + i] = run;
        g_cur[base + i] = run;
        run += c;
    }
    if (tid == 1023) g_off[NR_] = run;
}
__global__ void scatter_kernel(const int* __restrict__ eidx, const int* __restrict__ etype) {
    int e = blockIdx.x * blockDim.x + threadIdx.x;
    if (e >= EE_) return;
    int pos = atomicAdd(&g_cur[eidx[EE_ + e] * R_ + etype[e]], 1);
    g_elist[pos] = eidx[e];
}

__global__ void gather_mean_kernel(const float* __restrict__ tok, const int* __restrict__ wti) {
    long long t = (long long)blockIdx.x * blockDim.x + threadIdx.x;
    if (t >= (long long)NN_ * D_) return;
    int n = (int)(t / D_);
    int d = (int)(t % D_);
    const int* w = wti + n * TPW_;
    float s = tok[(size_t)w[0] * D_ + d] + tok[(size_t)w[1] * D_ + d]
            + tok[(size_t)w[2] * D_ + d] + tok[(size_t)w[3] * D_ + d];
    g_x[t] = 0.25f * s;
}

// one CTA per dst node, 192 threads; thread owns 4 feature columns.
__global__ void __launch_bounds__(192)
csr_agg_kernel(const float* __restrict__ x) {
    int dst = blockIdx.x;
    int d = threadIdx.x * 4;
#pragma unroll
    for (int r = 0; r < R_; ++r) {
        int beg = g_off[dst * R_ + r];
        int end = g_off[dst * R_ + r + 1];
        float4 a = make_float4(0.f, 0.f, 0.f, 0.f);
        for (int i = beg; i < end; ++i) {
            int src = g_elist[i];
            float4 v = *(const float4*)(x + (size_t)src * D_ + d);
            a.x += v.x; a.y += v.y; a.z += v.z; a.w += v.w;
        }
        float s = (end > beg) ? (1.f / (float)(end - beg)) : 0.f;
        a.x *= s; a.y *= s; a.z *= s; a.w *= s;
        *(float4*)(g_h + ((size_t)r * NN_ + dst) * D_ + d) = a;
    }
}

// ---------------- fp32 -> split bf16 conversions ----------------
// A_cat[n][k]: k in [0,3072)->g_h[r][n][d], [3072,3840)->xsrc[n][d]
__global__ void convertA_kernel(const float* __restrict__ xsrc) {
    long long t = (long long)blockIdx.x * blockDim.x + threadIdx.x;
    const long long TOT = (long long)NN_ * (KTOT_ / 2);
    if (t >= TOT) return;
    int n = (int)(t / (KTOT_ / 2));
    int k = (int)(t % (KTOT_ / 2)) * 2;
    int r = k / D_;
    int d = k % D_;
    const float* s = (r < 4) ? (g_h + ((size_t)r * NN_ + n) * D_ + d)
                             : (xsrc + (size_t)n * D_ + d);
    float v0 = s[0], v1 = s[1];
    uint32_t hp = pack2(v0, v1);
    uint32_t lp = pack2(v0 - __uint_as_float(hp << 16),
                        v1 - __uint_as_float(hp & 0xFFFF0000u));
    ((uint32_t*)g_ahi)[t] = hp;
    ((uint32_t*)g_alo)[t] = lp;
}
// Wcat[k][n]: Wrel flat (r*768+d)*768+n == k*768+n for k<3072; Wroot for the rest.
__global__ void convertW_kernel(const float* __restrict__ Wrel, const float* __restrict__ Wroot) {
    long long t = (long long)blockIdx.x * blockDim.x + threadIdx.x;
    const long long TOT = (long long)KTOT_ * D_ / 2;
    if (t >= TOT) return;
    long long i = t * 2;                    // flat [k][n] index
    const float* s = (i < (long long)3072 * D_) ? (Wrel + i)
                                                : (Wroot + (i - (long long)3072 * D_));
    float v0 = s[0], v1 = s[1];
    uint32_t hp = pack2(v0, v1);
    uint32_t lp = pack2(v0 - __uint_as_float(hp << 16),
                        v1 - __uint_as_float(hp & 0xFFFF0000u));
    ((uint32_t*)g_whi)[t] = hp;
    ((uint32_t*)g_wlo)[t] = lp;
}

// ---------------- split-bf16 tensor GEMM: cp.async + ldmatrix + mma ----------------
// C(NN_ x 768) = relu( A_cat @ Wcat + bias )
#define GBM 128
#define GBN 128
#define GBK 32
#define NSTG (KTOT_ / GBK)   // 120
#define APIT 80              // A row pitch bytes (64 data + 16 pad)
#define BPIT 528             // B row pitch bytes (256 data + 16 pad) = 132 u32
#define ASZB (GBM * APIT)    // 10240 bytes per A half
#define BSZB (GBK * BPIT)    // 16896 bytes per B half
#define SBUFB (2 * ASZB + 2 * BSZB)   // 54272 bytes per stage
#define GSMEM (3 * SBUFB)             // 162816 bytes

__global__ void __launch_bounds__(256, 1)
gemm_rgcn(const __nv_bfloat16* __restrict__ Ahi, const __nv_bfloat16* __restrict__ Alo,
          const __nv_bfloat16* __restrict__ Whi, const __nv_bfloat16* __restrict__ Wlo,
          const float* __restrict__ bias, float* __restrict__ C) {
    extern __shared__ char smem[];
    const uint32_t sb = smem_u32(smem);
    const int tid  = threadIdx.x;
    const int wid  = tid >> 5;
    const int lane = tid & 31;
    const int g    = lane >> 2;
    const int tc   = lane & 3;
    const int wm   = wid & 3;        // 0..3 -> 32-row slice
    const int wn   = wid >> 2;       // 0..1 -> 64-col slice
    const int m0   = blockIdx.y * GBM;
    const int n0   = blockIdx.x * GBN;
    const int l15  = lane & 15;
    const int lhi  = (lane >> 4) * 16;

    float acc[2][8][4];
#pragma unroll
    for (int i = 0; i < 2; ++i)
#pragma unroll
        for (int j = 0; j < 8; ++j)
#pragma unroll
            for (int q = 0; q < 4; ++q) acc[i][j][q] = 0.f;

    // per-thread load coordinates (2 chunks per array per stage)
    const int arow0 = tid >> 2,        aseg0 = (tid & 3);
    const int arow1 = (tid + 256) >> 2, aseg1 = ((tid + 256) & 3);
    const int brow0 = tid >> 4,        bseg0 = (tid & 15);
    const int brow1 = (tid + 256) >> 4, bseg1 = ((tid + 256) & 15);

    auto issue = [&](int kc, int buf) {
        const int k0 = kc * GBK;
        const uint32_t s = sb + buf * SBUFB;
        // A halves
        {
            const __nv_bfloat16* s0 = Ahi + (size_t)(m0 + arow0) * KTOT_ + k0 + aseg0 * 8;
            const __nv_bfloat16* s1 = Ahi + (size_t)(m0 + arow1) * KTOT_ + k0 + aseg1 * 8;
            const __nv_bfloat16* t0 = Alo + (size_t)(m0 + arow0) * KTOT_ + k0 + aseg0 * 8;
            const __nv_bfloat16* t1 = Alo + (size_t)(m0 + arow1) * KTOT_ + k0 + aseg1 * 8;
            cp16(s + arow0 * APIT + aseg0 * 16, s0);
            cp16(s + arow1 * APIT + aseg1 * 16, s1);
            cp16(s + ASZB + arow0 * APIT + aseg0 * 16, t0);
            cp16(s + ASZB + arow1 * APIT + aseg1 * 16, t1);
        }
        // B halves
        {
            const uint32_t bb = s + 2 * ASZB;
            const __nv_bfloat16* s0 = Whi + (size_t)(k0 + brow0) * D_ + n0 + bseg0 * 8;
            const __nv_bfloat16* s1 = Whi + (size_t)(k0 + brow1) * D_ + n0 + bseg1 * 8;
            const __nv_bfloat16* t0 = Wlo + (size_t)(k0 + brow0) * D_ + n0 + bseg0 * 8;
            const __nv_bfloat16* t1 = Wlo + (size_t)(k0 + brow1) * D_ + n0 + bseg1 * 8;
            cp16(bb + brow0 * BPIT + bseg0 * 16, s0);
            cp16(bb + brow1 * BPIT + bseg1 * 16, s1);
            cp16(bb + BSZB + brow0 * BPIT + bseg0 * 16, t0);
            cp16(bb + BSZB + brow1 * BPIT + bseg1 * 16, t1);
        }
    };

    issue(0, 0);
    asm volatile("cp.async.commit_group;" ::: "memory");
    issue(1, 1);
    asm volatile("cp.async.commit_group;" ::: "memory");

#pragma unroll 1
    for (int kc = 0; kc < NSTG; ++kc) {
        if (kc + 2 < NSTG) {
            issue(kc + 2, (kc + 2) % 3);
            asm volatile("cp.async.commit_group;" ::: "memory");
            asm volatile("cp.async.wait_group 2;" ::: "memory");
        } else {
            asm volatile("cp.async.wait_group 0;" ::: "memory");
        }
        __syncthreads();

        const uint32_t s = sb + (kc % 3) * SBUFB;
        const uint32_t aBaseH = s + (wm * 32 + l15) * APIT + lhi;
        const uint32_t bBaseH = s + 2 * ASZB + l15 * BPIT + (wn * 64) * 2 + lhi;

#pragma unroll
        for (int ks = 0; ks < 2; ++ks) {
            uint32_t aH[2][4], aL[2][4], bH[4][4], bL[4][4];
#pragma unroll
            for (int mt = 0; mt < 2; ++mt) {
                uint32_t ad = aBaseH + mt * (16 * APIT) + ks * 32;
                ldmx4(aH[mt], ad);
                ldmx4(aL[mt], ad + ASZB);
            }
#pragma unroll
            for (int p = 0; p < 4; ++p) {
                uint32_t bd = bBaseH + ks * (16 * BPIT) + p * 32;
                ldmx4t(bH[p], bd);
                ldmx4t(bL[p], bd + BSZB);
            }
#pragma unroll
            for (int mt = 0; mt < 2; ++mt)
#pragma unroll
                for (int nt = 0; nt < 8; ++nt) {
                    const int p = nt >> 1, h = (nt & 1) * 2;
                    uint32_t bh[2] = { bH[p][h], bH[p][h + 1] };
                    uint32_t bl[2] = { bL[p][h], bL[p][h + 1] };
                    mma16816(acc[mt][nt], aH[mt], bh);
                    mma16816(acc[mt][nt], aH[mt], bl);
                    mma16816(acc[mt][nt], aL[mt], bh);
                }
        }
        __syncthreads();
    }

    // ---- epilogue: bias + relu ----
#pragma unroll
    for (int mt = 0; mt < 2; ++mt) {
        int row = m0 + wm * 32 + mt * 16 + g;
#pragma unroll
        for (int nt = 0; nt < 8; ++nt) {
            int col = n0 + wn * 64 + nt * 8 + tc * 2;
            float b0 = __ldg(bias + col);
            float b1 = __ldg(bias + col + 1);
            float2 v0 = make_float2(fmaxf(acc[mt][nt][0] + b0, 0.f),
                                    fmaxf(acc[mt][nt][1] + b1, 0.f));
            float2 v1 = make_float2(fmaxf(acc[mt][nt][2] + b0, 0.f),
                                    fmaxf(acc[mt][nt][3] + b1, 0.f));
            *(float2*)(C + (size_t)row * D_ + col)       = v0;
            *(float2*)(C + (size_t)(row + 8) * D_ + col) = v1;
        }
    }
}

// ---------------- fp32 SGEMM for small head GEMMs ----------------
#define BM 128
#define BN 128
#define BK 8
#define TM 8
#define TN 8
__global__ __launch_bounds__(256)
void sgemm_acc(const float* __restrict__ A, const float* __restrict__ Bm,
               float* __restrict__ C, int M, int N, int K) {
    const int brow = blockIdx.y, bcol = blockIdx.x;
    const int tid = threadIdx.x;
    __shared__ float As[BK][BM];
    __shared__ float Bs[BK][BN];
    const int threadRow = tid / (BN / TN);
    const int threadCol = tid % (BN / TN);
    const int aRow = tid >> 1;
    const int aCol = (tid & 1) * 4;
    const int bRow = tid >> 5;
    const int bCol = (tid & 31) * 4;
    float acc[TM][TN] = {};
    float regM[TM], regN[TN];
    const int gARow = brow * BM + aRow;
    const bool aValid = (gARow < M);
    const float* Aptr = A + (size_t)gARow * K;
    const float* Bptr = Bm + bcol * BN;
    for (int k0 = 0; k0 < K; k0 += BK) {
        float4 av = aValid ? *(const float4*)(Aptr + k0 + aCol) : make_float4(0.f, 0.f, 0.f, 0.f);
        As[aCol + 0][aRow] = av.x;
        As[aCol + 1][aRow] = av.y;
        As[aCol + 2][aRow] = av.z;
        As[aCol + 3][aRow] = av.w;
        *(float4*)&Bs[bRow][bCol] = *(const float4*)(Bptr + (size_t)(k0 + bRow) * N + bCol);
        __syncthreads();
#pragma unroll
        for (int k = 0; k < BK; ++k) {
#pragma unroll
            for (int i = 0; i < TM; ++i) regM[i] = As[k][threadRow * TM + i];
#pragma unroll
            for (int j = 0; j < TN; ++j) regN[j] = Bs[k][threadCol * TN + j];
#pragma unroll
            for (int i = 0; i < TM; ++i)
#pragma unroll
                for (int j = 0; j < TN; ++j)
                    acc[i][j] += regM[i] * regN[j];
        }
        __syncthreads();
    }
#pragma unroll
    for (int i = 0; i < TM; ++i) {
        int r = brow * BM + threadRow * TM + i;
        if (r < M) {
            float* Cp = C + (size_t)r * N + bcol * BN + threadCol * TN;
#pragma unroll
            for (int j = 0; j < TN; j += 4) {
                float4 cv = *(float4*)(Cp + j);
                cv.x += acc[i][j + 0];
                cv.y += acc[i][j + 1];
                cv.z += acc[i][j + 2];
                cv.w += acc[i][j + 3];
                *(float4*)(Cp + j) = cv;
            }
        }
    }
}

// ---------------- head kernels ----------------
__global__ void ev_pool_kernel() {
    int t = blockIdx.x * blockDim.x + threadIdx.x;
    if (t >= SEQS_ * DOUT_) return;
    int s = t / DOUT_, d = t % DOUT_;
    const float* base = g_x + (size_t)s * WORDS_ * DOUT_ + d;
    float sum = 0.f, mx = -1e30f;
#pragma unroll 8
    for (int w = 0; w < WORDS_; ++w) {
        float v = base[(size_t)w * DOUT_];
        sum += v;
        mx = fmaxf(mx, v);
    }
    g_ev[s * (2 * DOUT_) + d]         = sum * (1.f / WORDS_);
    g_ev[s * (2 * DOUT_) + DOUT_ + d] = mx;
}
__global__ void build_attin_kernel(const float* __restrict__ tok, const int* __restrict__ csi) {
    int t = blockIdx.x * blockDim.x + threadIdx.x;
    const int W = D_ + 2 * DOUT_;
    if (t >= SEQS_ * W) return;
    int s = t / W, c = t % W;
    if (c < D_) {
        int seq = csi[s / EVI_];
        g_attin[t] = tok[(size_t)seq * L_ * D_ + c];
    } else {
        g_attin[t] = g_ev[s * (2 * DOUT_) + (c - D_)];
    }
}
__global__ void dotp_kernel(const float* __restrict__ att_w1) {
    int s = blockIdx.x;
    int tid = threadIdx.x;
    float acc = 0.f;
    for (int k = tid; k < DOUT_; k += 256)
        acc += g_hatt[(size_t)s * DOUT_ + k] * att_w1[k];
#pragma unroll
    for (int o = 16; o; o >>= 1) acc += __shfl_down_sync(0xffffffffu, acc, o);
    __shared__ float sw[8];
    if ((tid & 31) == 0) sw[tid >> 5] = acc;
    __syncthreads();
    if (tid == 0) {
        float r = 0.f;
#pragma unroll
        for (int w = 0; w < 8; ++w) r += sw[w];
        g_p[s] = r;
    }
}
__global__ void softmax_att_kernel(float* __restrict__ out) {
    int b = blockIdx.x;
    if (threadIdx.x != 0) return;
    float pv[EVI_];
    float m = -1e30f;
#pragma unroll
    for (int e = 0; e < EVI_; ++e) { pv[e] = g_p[b * EVI_ + e]; m = fmaxf(m, pv[e]); }
    float s = 0.f;
#pragma unroll
    for (int e = 0; e < EVI_; ++e) { pv[e] = expf(pv[e] - m); s += pv[e]; }
    float is = 1.f / s;
#pragma unroll
    for (int e = 0; e < EVI_; ++e) {
        g_a[b * EVI_ + e] = pv[e] * is;
        float p = g_p[b * EVI_ + e];
        out[B_ * NC_ + b * EVI_ + e] = 1.f / (1.f + expf(-p));
    }
}
__global__ void graph_rep_kernel(const float* __restrict__ concat_cls) {
    int t = blockIdx.x * blockDim.x + threadIdx.x;
    const int W = 2 * DOUT_ + D_;
    if (t >= B_ * W) return;
    int b = t / W, c = t % W;
    if (c < 2 * DOUT_) {
        float acc = 0.f;
#pragma unroll
        for (int e = 0; e < EVI_; ++e)
            acc += g_a[b * EVI_ + e] * g_ev[(size_t)(b * EVI_ + e) * (2 * DOUT_) + c];
        g_rep[t] = acc;
    } else {
        g_rep[t] = concat_cls[b * D_ + (c - 2 * DOUT_)];
    }
}
__global__ void final_kernel(const float* __restrict__ lin2_w,
                             const float* __restrict__ lin2_b,
                             float* __restrict__ out) {
    int b = blockIdx.x;
    int tid = threadIdx.x;
    float a0 = 0.f, a1 = 0.f, a2 = 0.f;
    for (int k = tid; k < LH_; k += 128) {
        float h = g_hid[(size_t)b * LH_ + k];
        a0 += h * lin2_w[k * NC_ + 0];
        a1 += h * lin2_w[k * NC_ + 1];
        a2 += h * lin2_w[k * NC_ + 2];
    }
#pragma unroll
    for (int o = 16; o; o >>= 1) {
        a0 += __shfl_down_sync(0xffffffffu, a0, o);
        a1 += __shfl_down_sync(0xffffffffu, a1, o);
        a2 += __shfl_down_sync(0xffffffffu, a2, o);
    }
    __shared__ float s0[4], s1[4], s2[4];
    if ((tid & 31) == 0) { int w = tid >> 5; s0[w] = a0; s1[w] = a1; s2[w] = a2; }
    __syncthreads();
    if (tid == 0) {
        float l0 = s0[0] + s0[1] + s0[2] + s0[3] + lin2_b[0];
        float l1 = s1[0] + s1[1] + s1[2] + s1[3] + lin2_b[1];
        float l2 = s2[0] + s2[1] + s2[2] + s2[3] + lin2_b[2];
        float m = fmaxf(l0, fmaxf(l1, l2));
        float lse = logf(expf(l0 - m) + expf(l1 - m) + expf(l2 - m)) + m;
        out[b * NC_ + 0] = l0 - lse;
        out[b * NC_ + 1] = l1 - lse;
        out[b * NC_ + 2] = l2 - lse;
    }
}

// ---------------- launch ----------------
static inline dim3 gemm_grid_f32(int M, int N) {
    return dim3((N + BN - 1) / BN, (M + BM - 1) / BM);
}

extern "C" void kernel_launch(void* const* d_in, const int* in_sizes, int n_in,
                              void* d_out, int out_size) {
    const float* token_feats = (const float*)d_in[0];
    const float* concat_cls  = (const float*)d_in[1];
    const float* W_rel1      = (const float*)d_in[2];
    const float* W_root1     = (const float*)d_in[3];
    const float* b1          = (const float*)d_in[4];
    const float* W_rel2      = (const float*)d_in[5];
    const float* W_root2     = (const float*)d_in[6];
    const float* b2          = (const float*)d_in[7];
    const float* att_w0      = (const float*)d_in[8];
    const float* att_w1      = (const float*)d_in[9];
    const float* lin1_w      = (const float*)d_in[10];
    const float* lin1_b      = (const float*)d_in[11];
    const float* lin2_w      = (const float*)d_in[12];
    const float* lin2_b      = (const float*)d_in[13];
    const int*   wti         = (const int*)d_in[14];
    const int*   eidx        = (const int*)d_in[15];
    const int*   etype       = (const int*)d_in[16];
    const int*   csi         = (const int*)d_in[17];
    float* out = (float*)d_out;

    float *p_x, *p_acc, *p_attin, *p_hatt, *p_rep, *p_hid;
    int* p_cnt;
    __nv_bfloat16 *p_ahi, *p_alo, *p_whi, *p_wlo;
    cudaGetSymbolAddress((void**)&p_x,     g_x);
    cudaGetSymbolAddress((void**)&p_acc,   g_acc);
    cudaGetSymbolAddress((void**)&p_cnt,   g_cnt);
    cudaGetSymbolAddress((void**)&p_attin, g_attin);
    cudaGetSymbolAddress((void**)&p_hatt,  g_hatt);
    cudaGetSymbolAddress((void**)&p_rep,   g_rep);
    cudaGetSymbolAddress((void**)&p_hid,   g_hid);
    cudaGetSymbolAddress((void**)&p_ahi,   g_ahi);
    cudaGetSymbolAddress((void**)&p_alo,   g_alo);
    cudaGetSymbolAddress((void**)&p_whi,   g_whi);
    cudaGetSymbolAddress((void**)&p_wlo,   g_wlo);

    cudaFuncSetAttribute(gemm_rgcn, cudaFuncAttributeMaxDynamicSharedMemorySize, GSMEM);

    const int T = 256;
    const long long ND  = (long long)NN_ * D_;
    const long long CVA = (long long)NN_ * (KTOT_ / 2);
    const long long CVW = (long long)KTOT_ * D_ / 2;
    const dim3 ggrid(D_ / GBN, NN_ / GBM);   // (6, 80)

    // --- graph prep: CSR ---
    zero4_kernel<<<(NR_ / 4 + T - 1) / T, T>>>((float4*)p_cnt, NR_ / 4);
    count_kernel<<<(EE_ + T - 1) / T, T>>>(eidx, etype);
    scan_kernel<<<1, 1024>>>();
    scatter_kernel<<<(EE_ + T - 1) / T, T>>>(eidx, etype);

    // --- x0 ---
    gather_mean_kernel<<<(unsigned)((ND + T - 1) / T), T>>>(token_feats, wti);

    // --- layer 1 ---
    csr_agg_kernel<<<NN_, 192>>>(p_x);
    convertW_kernel<<<(unsigned)((CVW + T - 1) / T), T>>>(W_rel1, W_root1);
    convertA_kernel<<<(unsigned)((CVA + T - 1) / T), T>>>(p_x);
    gemm_rgcn<<<ggrid, 256, GSMEM>>>(p_ahi, p_alo, p_whi, p_wlo, b1, p_acc);

    // --- layer 2 ---
    csr_agg_kernel<<<NN_, 192>>>(p_acc);
    convertW_kernel<<<(unsigned)((CVW + T - 1) / T), T>>>(W_rel2, W_root2);
    convertA_kernel<<<(unsigned)((CVA + T - 1) / T), T>>>(p_acc);
    gemm_rgcn<<<ggrid, 256, GSMEM>>>(p_ahi, p_alo, p_whi, p_wlo, b2, p_x);

    // --- evidence pooling + attention ---
    ev_pool_kernel<<<(SEQS_ * DOUT_ + T - 1) / T, T>>>();
    build_attin_kernel<<<(SEQS_ * (D_ + 2 * DOUT_) + T - 1) / T, T>>>(token_feats, csi);
    zero4_kernel<<<(SEQS_ * DOUT_ / 4 + T - 1) / T, T>>>((float4*)p_hatt, SEQS_ * DOUT_ / 4);
    sgemm_acc<<<gemm_grid_f32(SEQS_, DOUT_), 256>>>(p_attin, att_w0, p_hatt,
                                                    SEQS_, DOUT_, D_ + 2 * DOUT_);
    relu_kernel<<<(SEQS_ * DOUT_ + T - 1) / T, T>>>(p_hatt, (long long)SEQS_ * DOUT_);
    dotp_kernel<<<SEQS_, 256>>>(att_w1);
    softmax_att_kernel<<<B_, 32>>>(out);

    // --- graph readout + classifier ---
    graph_rep_kernel<<<(B_ * (2 * DOUT_ + D_) + T - 1) / T, T>>>(concat_cls);
    init_bias_kernel<<<(B_ * LH_ + T - 1) / T, T>>>(p_hid, lin1_b, B_, LH_);
    sgemm_acc<<<gemm_grid_f32(B_, LH_), 256>>>(p_rep, lin1_w, p_hid, B_, LH_, 2 * DOUT_ + D_);
    relu_kernel<<<(B_ * LH_ + T - 1) / T, T>>>(p_hid, (long long)B_ * LH_);
    final_kernel<<<B_, 128>>>(lin2_w, lin2_b, out);
}

// round 6
// speedup vs baseline: 1.1913x; 1.1913x over previous
#include <cuda_runtime.h>
#include <cuda_bf16.h>
#include <math.h>
#include <stdint.h>

// ---------------- problem constants ----------------
#define B_      64
#define EVI_    5
#define SEQS_   (B_ * EVI_)          // 320
#define L_      256
#define D_      768
#define WORDS_  32
#define TPW_    4
#define NN_     (SEQS_ * WORDS_)     // 10240 nodes
#define EE_     (NN_ * 16)           // 163840 edges
#define R_      4
#define DOUT_   768
#define LH_     1024
#define NC_     3
#define KTOT_   (5 * D_)             // 3840 fused K
#define NR_     (NN_ * R_)           // 40960 segments
#define KP2_    (KTOT_ / 2)          // 1920 k-pairs

// ---------------- scratch (device globals; no allocs allowed) ----------------
__device__ float g_x   [(size_t)NN_ * D_];          // x0 / x2
__device__ float g_acc [(size_t)NN_ * D_];          // x1
__device__ float g_h   [(size_t)R_ * NN_ * D_];     // per-relation aggregation
__device__ uint32_t g_bhi[(size_t)KP2_ * D_];       // B hi, k-pair packed [k2][n]
__device__ uint32_t g_blo[(size_t)KP2_ * D_];       // B lo
__device__ int   g_cnt [NR_];
__device__ int   g_off [NR_ + 1];
__device__ int   g_cur [NR_];
__device__ int   g_elist[EE_];
__device__ float g_ev  [SEQS_ * 2 * DOUT_];
__device__ float g_attin[SEQS_ * (D_ + 2 * DOUT_)];
__device__ float g_hatt[SEQS_ * DOUT_];
__device__ float g_p   [SEQS_];
__device__ float g_a   [SEQS_];
__device__ float g_rep [B_ * (2 * DOUT_ + D_)];
__device__ float g_hid [B_ * LH_];

// ---------------- small device helpers ----------------
__device__ __forceinline__ uint32_t smem_u32(const void* p) {
    uint32_t a;
    asm("{ .reg .u64 t; cvta.to.shared.u64 t, %1; cvt.u32.u64 %0, t; }" : "=r"(a) : "l"(p));
    return a;
}
__device__ __forceinline__ uint32_t pack2(float lo, float hi) {
    uint32_t r;
    asm("cvt.rn.bf16x2.f32 %0, %1, %2;" : "=r"(r) : "f"(hi), "f"(lo));
    return r;
}
__device__ __forceinline__ void mma16816(float* c, const uint32_t* a, const uint32_t* b) {
    asm volatile("mma.sync.aligned.m16n8k16.row.col.f32.bf16.bf16.f32 "
                 "{%0,%1,%2,%3}, {%4,%5,%6,%7}, {%8,%9}, {%0,%1,%2,%3};"
                 : "+f"(c[0]), "+f"(c[1]), "+f"(c[2]), "+f"(c[3])
                 : "r"(a[0]), "r"(a[1]), "r"(a[2]), "r"(a[3]), "r"(b[0]), "r"(b[1]));
}
__device__ __forceinline__ void cp16(uint32_t dst, const void* src) {
    asm volatile("cp.async.cg.shared.global [%0], [%1], 16;" :: "r"(dst), "l"(src));
}

// ---------------- utility kernels ----------------
__global__ void zero4_kernel(float4* p, long long n4) {
    long long t = (long long)blockIdx.x * blockDim.x + threadIdx.x;
    if (t < n4) p[t] = make_float4(0.f, 0.f, 0.f, 0.f);
}
__global__ void relu_kernel(float* p, long long n) {
    long long t = (long long)blockIdx.x * blockDim.x + threadIdx.x;
    if (t < n) p[t] = fmaxf(p[t], 0.f);
}
__global__ void init_bias_kernel(float* C, const float* __restrict__ bias, long long M, int N) {
    long long t = (long long)blockIdx.x * blockDim.x + threadIdx.x;
    if (t < M * N) C[t] = bias[t % N];
}

// ---------------- graph prep: counts -> scan -> scatter (CSR) ----------------
__global__ void count_kernel(const int* __restrict__ eidx, const int* __restrict__ etype) {
    int e = blockIdx.x * blockDim.x + threadIdx.x;
    if (e >= EE_) return;
    atomicAdd(&g_cnt[eidx[EE_ + e] * R_ + etype[e]], 1);
}
__global__ void scan_kernel() {
    __shared__ int part[1024];
    int tid = threadIdx.x;
    int base = tid * 40;
    int s = 0;
#pragma unroll 8
    for (int i = 0; i < 40; ++i) s += g_cnt[base + i];
    part[tid] = s;
    __syncthreads();
    for (int o = 1; o < 1024; o <<= 1) {
        int v = (tid >= o) ? part[tid - o] : 0;
        __syncthreads();
        part[tid] += v;
        __syncthreads();
    }
    int run = tid ? part[tid - 1] : 0;
#pragma unroll 8
    for (int i = 0; i < 40; ++i) {
        int c = g_cnt[base + i];
        g_off[base + i] = run;
        g_cur[base + i] = run;
        run += c;
    }
    if (tid == 1023) g_off[NR_] = run;
}
__global__ void scatter_kernel(const int* __restrict__ eidx, const int* __restrict__ etype) {
    int e = blockIdx.x * blockDim.x + threadIdx.x;
    if (e >= EE_) return;
    int pos = atomicAdd(&g_cur[eidx[EE_ + e] * R_ + etype[e]], 1);
    g_elist[pos] = eidx[e];
}

__global__ void gather_mean_kernel(const float* __restrict__ tok, const int* __restrict__ wti) {
    long long t = (long long)blockIdx.x * blockDim.x + threadIdx.x;
    if (t >= (long long)NN_ * D_) return;
    int n = (int)(t / D_);
    int d = (int)(t % D_);
    const int* w = wti + n * TPW_;
    float s = tok[(size_t)w[0] * D_ + d] + tok[(size_t)w[1] * D_ + d]
            + tok[(size_t)w[2] * D_ + d] + tok[(size_t)w[3] * D_ + d];
    g_x[t] = 0.25f * s;
}

// one CTA per dst node, 192 threads; thread owns 4 feature columns.
__global__ void __launch_bounds__(192)
csr_agg_kernel(const float* __restrict__ x) {
    int dst = blockIdx.x;
    int d = threadIdx.x * 4;
#pragma unroll
    for (int r = 0; r < R_; ++r) {
        int beg = g_off[dst * R_ + r];
        int end = g_off[dst * R_ + r + 1];
        float4 a = make_float4(0.f, 0.f, 0.f, 0.f);
        for (int i = beg; i < end; ++i) {
            int src = g_elist[i];
            float4 v = *(const float4*)(x + (size_t)src * D_ + d);
            a.x += v.x; a.y += v.y; a.z += v.z; a.w += v.w;
        }
        float s = (end > beg) ? (1.f / (float)(end - beg)) : 0.f;
        a.x *= s; a.y *= s; a.z *= s; a.w *= s;
        *(float4*)(g_h + ((size_t)r * NN_ + dst) * D_ + d) = a;
    }
}

// ---------------- B pre-pack: Wcat(3840x768) -> k-pair packed split bf16 ----------------
__global__ void convertB_kernel(const float* __restrict__ Wrel, const float* __restrict__ Wroot) {
    int t = blockIdx.x * blockDim.x + threadIdx.x;
    if (t >= KP2_ * D_) return;
    int k2 = t / D_;
    int n  = t - k2 * D_;
    int k  = 2 * k2;
    const float* bp = (k < 4 * D_) ? (Wrel + (size_t)k * D_ + n)
                                   : (Wroot + (size_t)(k - 4 * D_) * D_ + n);
    float v0 = bp[0], v1 = bp[D_];
    uint32_t hp = pack2(v0, v1);
    uint32_t lp = pack2(v0 - __uint_as_float(hp << 16),
                        v1 - __uint_as_float(hp & 0xFFFF0000u));
    g_bhi[t] = hp;
    g_blo[t] = lp;
}

// ---------------- split-bf16 tensor GEMM: A reg-staged, B cp.async ----------------
// C(NN_ x 768) = relu( [h0|h1|h2|h3|x](NN_ x 3840) @ Wcat + bias )
#define GBM 128
#define GBN 256
#define GBK 32
#define NSTG (KTOT_ / GBK)   // 120
#define AP_  20              // A smem pitch u32 (16 k-pairs + 4 pad)
#define BP_  264             // B smem pitch u32 (256 + 8 pad)
#define ASZ_ (GBM * AP_)     // 2560 u32
#define BSZ_ (16 * BP_)      // 4224 u32
#define SBUF (2 * ASZ_ + 2 * BSZ_)   // 13568 u32 per stage
#define GSMEM (2 * SBUF * 4)         // 108544 bytes

__global__ void __launch_bounds__(256, 1)
gemm_rgcn(const float* __restrict__ gh, const float* __restrict__ xroot,
          const uint32_t* __restrict__ Bhi, const uint32_t* __restrict__ Blo,
          const float* __restrict__ bias, float* __restrict__ C) {
    extern __shared__ uint32_t sm[];
    const uint32_t sb = smem_u32(sm);
    const int tid  = threadIdx.x;
    const int wid  = tid >> 5;
    const int lane = tid & 31;
    const int g    = lane >> 2;
    const int tc   = lane & 3;
    const int wm   = wid & 3;        // 0..3 -> 32-row slice
    const int wn   = wid >> 2;       // 0..1 -> 128-col slice
    const int m0   = blockIdx.y * GBM;
    const int n0   = blockIdx.x * GBN;

    float acc[2][16][4];
#pragma unroll
    for (int i = 0; i < 2; ++i)
#pragma unroll
        for (int j = 0; j < 16; ++j)
#pragma unroll
            for (int q = 0; q < 4; ++q) acc[i][j][q] = 0.f;

    float4 pa[4];

    auto prefetchA = [&](int kc) {
        const int k0 = kc * GBK;
        const int r  = k0 / D_;
        const int d0 = k0 - r * D_;
        const float* Ab = (r < 4) ? (gh + ((size_t)r * NN_ + m0) * D_ + d0)
                                  : (xroot + (size_t)m0 * D_ + d0);
#pragma unroll
        for (int i = 0; i < 4; ++i) {
            int c = tid + i * 256;
            int m = c >> 3, kq = c & 7;
            pa[i] = *(const float4*)(Ab + (size_t)m * D_ + kq * 4);
        }
    };
    auto storeA = [&](uint32_t* buf) {
        uint32_t* AsH = buf;
        uint32_t* AsL = buf + ASZ_;
#pragma unroll
        for (int i = 0; i < 4; ++i) {
            int c = tid + i * 256;
            int m = c >> 3, kq = c & 7;
            float4 v = pa[i];
            uint32_t h0 = pack2(v.x, v.y);
            uint32_t h1 = pack2(v.z, v.w);
            uint32_t l0 = pack2(v.x - __uint_as_float(h0 << 16),
                                v.y - __uint_as_float(h0 & 0xFFFF0000u));
            uint32_t l1 = pack2(v.z - __uint_as_float(h1 << 16),
                                v.w - __uint_as_float(h1 & 0xFFFF0000u));
            int off = m * AP_ + kq * 2;
            *(uint2*)&AsH[off] = make_uint2(h0, h1);
            *(uint2*)&AsL[off] = make_uint2(l0, l1);
        }
    };
    auto issueB = [&](int kc, int buf) {
        const int kp0 = kc * 16;
        const uint32_t bbH = sb + (uint32_t)buf * (SBUF * 4) + 2 * ASZ_ * 4;
        const uint32_t bbL = bbH + BSZ_ * 4;
#pragma unroll
        for (int i = 0; i < 4; ++i) {
            int c = tid + i * 256;
            int row = c >> 6, seg = c & 63;
            size_t gidx = (size_t)(kp0 + row) * D_ + n0 + seg * 4;
            uint32_t doff = row * (BP_ * 4) + seg * 16;
            cp16(bbH + doff, Bhi + gidx);
            cp16(bbL + doff, Blo + gidx);
        }
    };
    auto compute = [&](const uint32_t* s) {
        const uint32_t* AsH = s;
        const uint32_t* AsL = s + ASZ_;
        const uint32_t* BsH = s + 2 * ASZ_;
        const uint32_t* BsL = s + 2 * ASZ_ + BSZ_;
#pragma unroll
        for (int ks = 0; ks < 2; ++ks) {
            const int kb = ks * 8;
            uint32_t aH[2][4], aL[2][4];
#pragma unroll
            for (int mt = 0; mt < 2; ++mt) {
                int i0 = (wm * 32 + mt * 16 + g) * AP_ + kb + tc;
                int i1 = i0 + 8 * AP_;
                aH[mt][0] = AsH[i0]; aH[mt][1] = AsH[i1];
                aH[mt][2] = AsH[i0 + 4]; aH[mt][3] = AsH[i1 + 4];
                aL[mt][0] = AsL[i0]; aL[mt][1] = AsL[i1];
                aL[mt][2] = AsL[i0 + 4]; aL[mt][3] = AsL[i1 + 4];
            }
#pragma unroll
            for (int ng = 0; ng < 4; ++ng) {
                uint32_t bh[4][2], bl[4][2];
#pragma unroll
                for (int q = 0; q < 4; ++q) {
                    int cb = wn * 128 + (ng * 4 + q) * 8;
                    int j0 = (kb + tc) * BP_ + cb + g;
                    int j1 = j0 + 4 * BP_;
                    bh[q][0] = BsH[j0]; bh[q][1] = BsH[j1];
                    bl[q][0] = BsL[j0]; bl[q][1] = BsL[j1];
                }
#pragma unroll
                for (int mt = 0; mt < 2; ++mt)
#pragma unroll
                    for (int q = 0; q < 4; ++q) {
                        float* a = acc[mt][ng * 4 + q];
                        mma16816(a, aH[mt], bh[q]);
                        mma16816(a, aH[mt], bl[q]);
                        mma16816(a, aL[mt], bh[q]);
                    }
            }
        }
    };

    // ---- pipeline: A reg double-buffer, B cp.async double-buffer ----
    prefetchA(0);
    storeA(sm);
    issueB(0, 0);
    asm volatile("cp.async.commit_group;" ::: "memory");

#pragma unroll 1
    for (int kc = 0; kc < NSTG; ++kc) {
        const int cur = kc & 1;
        if (kc + 1 < NSTG) {
            issueB(kc + 1, 1 - cur);
            asm volatile("cp.async.commit_group;" ::: "memory");
            prefetchA(kc + 1);
            asm volatile("cp.async.wait_group 1;" ::: "memory");
        } else {
            asm volatile("cp.async.wait_group 0;" ::: "memory");
        }
        __syncthreads();
        compute(sm + cur * SBUF);
        if (kc + 1 < NSTG) storeA(sm + (1 - cur) * SBUF);
        __syncthreads();
    }

    // ---- epilogue: bias + relu ----
#pragma unroll
    for (int mt = 0; mt < 2; ++mt) {
        int row = m0 + wm * 32 + mt * 16 + g;
#pragma unroll
        for (int nt = 0; nt < 16; ++nt) {
            int col = n0 + wn * 128 + nt * 8 + tc * 2;
            float b0 = __ldg(bias + col);
            float b1 = __ldg(bias + col + 1);
            float2 v0 = make_float2(fmaxf(acc[mt][nt][0] + b0, 0.f),
                                    fmaxf(acc[mt][nt][1] + b1, 0.f));
            float2 v1 = make_float2(fmaxf(acc[mt][nt][2] + b0, 0.f),
                                    fmaxf(acc[mt][nt][3] + b1, 0.f));
            *(float2*)(C + (size_t)row * D_ + col)       = v0;
            *(float2*)(C + (size_t)(row + 8) * D_ + col) = v1;
        }
    }
}

// ---------------- fp32 SGEMM for small head GEMMs ----------------
#define BM 128
#define BN 128
#define BK 8
#define TM 8
#define TN 8
__global__ __launch_bounds__(256)
void sgemm_acc(const float* __restrict__ A, const float* __restrict__ Bm,
               float* __restrict__ C, int M, int N, int K) {
    const int brow = blockIdx.y, bcol = blockIdx.x;
    const int tid = threadIdx.x;
    __shared__ float As[BK][BM];
    __shared__ float Bs[BK][BN];
    const int threadRow = tid / (BN / TN);
    const int threadCol = tid % (BN / TN);
    const int aRow = tid >> 1;
    const int aCol = (tid & 1) * 4;
    const int bRow = tid >> 5;
    const int bCol = (tid & 31) * 4;
    float acc[TM][TN] = {};
    float regM[TM], regN[TN];
    const int gARow = brow * BM + aRow;
    const bool aValid = (gARow < M);
    const float* Aptr = A + (size_t)gARow * K;
    const float* Bptr = Bm + bcol * BN;
    for (int k0 = 0; k0 < K; k0 += BK) {
        float4 av = aValid ? *(const float4*)(Aptr + k0 + aCol) : make_float4(0.f, 0.f, 0.f, 0.f);
        As[aCol + 0][aRow] = av.x;
        As[aCol + 1][aRow] = av.y;
        As[aCol + 2][aRow] = av.z;
        As[aCol + 3][aRow] = av.w;
        *(float4*)&Bs[bRow][bCol] = *(const float4*)(Bptr + (size_t)(k0 + bRow) * N + bCol);
        __syncthreads();
#pragma unroll
        for (int k = 0; k < BK; ++k) {
#pragma unroll
            for (int i = 0; i < TM; ++i) regM[i] = As[k][threadRow * TM + i];
#pragma unroll
            for (int j = 0; j < TN; ++j) regN[j] = Bs[k][threadCol * TN + j];
#pragma unroll
            for (int i = 0; i < TM; ++i)
#pragma unroll
                for (int j = 0; j < TN; ++j)
                    acc[i][j] += regM[i] * regN[j];
        }
        __syncthreads();
    }
#pragma unroll
    for (int i = 0; i < TM; ++i) {
        int r = brow * BM + threadRow * TM + i;
        if (r < M) {
            float* Cp = C + (size_t)r * N + bcol * BN + threadCol * TN;
#pragma unroll
            for (int j = 0; j < TN; j += 4) {
                float4 cv = *(float4*)(Cp + j);
                cv.x += acc[i][j + 0];
                cv.y += acc[i][j + 1];
                cv.z += acc[i][j + 2];
                cv.w += acc[i][j + 3];
                *(float4*)(Cp + j) = cv;
            }
        }
    }
}

// ---------------- head kernels ----------------
__global__ void ev_pool_kernel() {
    int t = blockIdx.x * blockDim.x + threadIdx.x;
    if (t >= SEQS_ * DOUT_) return;
    int s = t / DOUT_, d = t % DOUT_;
    const float* base = g_x + (size_t)s * WORDS_ * DOUT_ + d;
    float sum = 0.f, mx = -1e30f;
#pragma unroll 8
    for (int w = 0; w < WORDS_; ++w) {
        float v = base[(size_t)w * DOUT_];
        sum += v;
        mx = fmaxf(mx, v);
    }
    g_ev[s * (2 * DOUT_) + d]         = sum * (1.f / WORDS_);
    g_ev[s * (2 * DOUT_) + DOUT_ + d] = mx;
}
__global__ void build_attin_kernel(const float* __restrict__ tok, const int* __restrict__ csi) {
    int t = blockIdx.x * blockDim.x + threadIdx.x;
    const int W = D_ + 2 * DOUT_;
    if (t >= SEQS_ * W) return;
    int s = t / W, c = t % W;
    if (c < D_) {
        int seq = csi[s / EVI_];
        g_attin[t] = tok[(size_t)seq * L_ * D_ + c];
    } else {
        g_attin[t] = g_ev[s * (2 * DOUT_) + (c - D_)];
    }
}
__global__ void dotp_kernel(const float* __restrict__ att_w1) {
    int s = blockIdx.x;
    int tid = threadIdx.x;
    float acc = 0.f;
    for (int k = tid; k < DOUT_; k += 256)
        acc += g_hatt[(size_t)s * DOUT_ + k] * att_w1[k];
#pragma unroll
    for (int o = 16; o; o >>= 1) acc += __shfl_down_sync(0xffffffffu, acc, o);
    __shared__ float sw[8];
    if ((tid & 31) == 0) sw[tid >> 5] = acc;
    __syncthreads();
    if (tid == 0) {
        float r = 0.f;
#pragma unroll
        for (int w = 0; w < 8; ++w) r += sw[w];
        g_p[s] = r;
    }
}
__global__ void softmax_att_kernel(float* __restrict__ out) {
    int b = blockIdx.x;
    if (threadIdx.x != 0) return;
    float pv[EVI_];
    float m = -1e30f;
#pragma unroll
    for (int e = 0; e < EVI_; ++e) { pv[e] = g_p[b * EVI_ + e]; m = fmaxf(m, pv[e]); }
    float s = 0.f;
#pragma unroll
    for (int e = 0; e < EVI_; ++e) { pv[e] = expf(pv[e] - m); s += pv[e]; }
    float is = 1.f / s;
#pragma unroll
    for (int e = 0; e < EVI_; ++e) {
        g_a[b * EVI_ + e] = pv[e] * is;
        float p = g_p[b * EVI_ + e];
        out[B_ * NC_ + b * EVI_ + e] = 1.f / (1.f + expf(-p));
    }
}
__global__ void graph_rep_kernel(const float* __restrict__ concat_cls) {
    int t = blockIdx.x * blockDim.x + threadIdx.x;
    const int W = 2 * DOUT_ + D_;
    if (t >= B_ * W) return;
    int b = t / W, c = t % W;
    if (c < 2 * DOUT_) {
        float acc = 0.f;
#pragma unroll
        for (int e = 0; e < EVI_; ++e)
            acc += g_a[b * EVI_ + e] * g_ev[(size_t)(b * EVI_ + e) * (2 * DOUT_) + c];
        g_rep[t] = acc;
    } else {
        g_rep[t] = concat_cls[b * D_ + (c - 2 * DOUT_)];
    }
}
__global__ void final_kernel(const float* __restrict__ lin2_w,
                             const float* __restrict__ lin2_b,
                             float* __restrict__ out) {
    int b = blockIdx.x;
    int tid = threadIdx.x;
    float a0 = 0.f, a1 = 0.f, a2 = 0.f;
    for (int k = tid; k < LH_; k += 128) {
        float h = g_hid[(size_t)b * LH_ + k];
        a0 += h * lin2_w[k * NC_ + 0];
        a1 += h * lin2_w[k * NC_ + 1];
        a2 += h * lin2_w[k * NC_ + 2];
    }
#pragma unroll
    for (int o = 16; o; o >>= 1) {
        a0 += __shfl_down_sync(0xffffffffu, a0, o);
        a1 += __shfl_down_sync(0xffffffffu, a1, o);
        a2 += __shfl_down_sync(0xffffffffu, a2, o);
    }
    __shared__ float s0[4], s1[4], s2[4];
    if ((tid & 31) == 0) { int w = tid >> 5; s0[w] = a0; s1[w] = a1; s2[w] = a2; }
    __syncthreads();
    if (tid == 0) {
        float l0 = s0[0] + s0[1] + s0[2] + s0[3] + lin2_b[0];
        float l1 = s1[0] + s1[1] + s1[2] + s1[3] + lin2_b[1];
        float l2 = s2[0] + s2[1] + s2[2] + s2[3] + lin2_b[2];
        float m = fmaxf(l0, fmaxf(l1, l2));
        float lse = logf(expf(l0 - m) + expf(l1 - m) + expf(l2 - m)) + m;
        out[b * NC_ + 0] = l0 - lse;
        out[b * NC_ + 1] = l1 - lse;
        out[b * NC_ + 2] = l2 - lse;
    }
}

// ---------------- launch ----------------
static inline dim3 gemm_grid_f32(int M, int N) {
    return dim3((N + BN - 1) / BN, (M + BM - 1) / BM);
}

extern "C" void kernel_launch(void* const* d_in, const int* in_sizes, int n_in,
                              void* d_out, int out_size) {
    const float* token_feats = (const float*)d_in[0];
    const float* concat_cls  = (const float*)d_in[1];
    const float* W_rel1      = (const float*)d_in[2];
    const float* W_root1     = (const float*)d_in[3];
    const float* b1          = (const float*)d_in[4];
    const float* W_rel2      = (const float*)d_in[5];
    const float* W_root2     = (const float*)d_in[6];
    const float* b2          = (const float*)d_in[7];
    const float* att_w0      = (const float*)d_in[8];
    const float* att_w1      = (const float*)d_in[9];
    const float* lin1_w      = (const float*)d_in[10];
    const float* lin1_b      = (const float*)d_in[11];
    const float* lin2_w      = (const float*)d_in[12];
    const float* lin2_b      = (const float*)d_in[13];
    const int*   wti         = (const int*)d_in[14];
    const int*   eidx        = (const int*)d_in[15];
    const int*   etype       = (const int*)d_in[16];
    const int*   csi         = (const int*)d_in[17];
    float* out = (float*)d_out;

    float *p_x, *p_acc, *p_h, *p_attin, *p_hatt, *p_rep, *p_hid;
    int* p_cnt;
    uint32_t *p_bhi, *p_blo;
    cudaGetSymbolAddress((void**)&p_x,     g_x);
    cudaGetSymbolAddress((void**)&p_acc,   g_acc);
    cudaGetSymbolAddress((void**)&p_h,     g_h);
    cudaGetSymbolAddress((void**)&p_cnt,   g_cnt);
    cudaGetSymbolAddress((void**)&p_attin, g_attin);
    cudaGetSymbolAddress((void**)&p_hatt,  g_hatt);
    cudaGetSymbolAddress((void**)&p_rep,   g_rep);
    cudaGetSymbolAddress((void**)&p_hid,   g_hid);
    cudaGetSymbolAddress((void**)&p_bhi,   g_bhi);
    cudaGetSymbolAddress((void**)&p_blo,   g_blo);

    cudaFuncSetAttribute(gemm_rgcn, cudaFuncAttributeMaxDynamicSharedMemorySize, GSMEM);

    const int T = 256;
    const long long ND = (long long)NN_ * D_;
    const int CVB = KP2_ * D_;
    const dim3 ggrid(D_ / GBN, NN_ / GBM);   // (3, 80)

    // --- graph prep: CSR ---
    zero4_kernel<<<(NR_ / 4 + T - 1) / T, T>>>((float4*)p_cnt, NR_ / 4);
    count_kernel<<<(EE_ + T - 1) / T, T>>>(eidx, etype);
    scan_kernel<<<1, 1024>>>();
    scatter_kernel<<<(EE_ + T - 1) / T, T>>>(eidx, etype);

    // --- x0 ---
    gather_mean_kernel<<<(unsigned)((ND + T - 1) / T), T>>>(token_feats, wti);

    // --- layer 1 ---
    csr_agg_kernel<<<NN_, 192>>>(p_x);
    convertB_kernel<<<(CVB + T - 1) / T, T>>>(W_rel1, W_root1);
    gemm_rgcn<<<ggrid, 256, GSMEM>>>(p_x ? p_h : p_h, p_x, p_bhi, p_blo, b1, p_acc);

    // --- layer 2 ---
    csr_agg_kernel<<<NN_, 192>>>(p_acc);
    convertB_kernel<<<(CVB + T - 1) / T, T>>>(W_rel2, W_root2);
    gemm_rgcn<<<ggrid, 256, GSMEM>>>(p_h, p_acc, p_bhi, p_blo, b2, p_x);

    // --- evidence pooling + attention ---
    ev_pool_kernel<<<(SEQS_ * DOUT_ + T - 1) / T, T>>>();
    build_attin_kernel<<<(SEQS_ * (D_ + 2 * DOUT_) + T - 1) / T, T>>>(token_feats, csi);
    zero4_kernel<<<(SEQS_ * DOUT_ / 4 + T - 1) / T, T>>>((float4*)p_hatt, SEQS_ * DOUT_ / 4);
    sgemm_acc<<<gemm_grid_f32(SEQS_, DOUT_), 256>>>(p_attin, att_w0, p_hatt,
                                                    SEQS_, DOUT_, D_ + 2 * DOUT_);
    relu_kernel<<<(SEQS_ * DOUT_ + T - 1) / T, T>>>(p_hatt, (long long)SEQS_ * DOUT_);
    dotp_kernel<<<SEQS_, 256>>>(att_w1);
    softmax_att_kernel<<<B_, 32>>>(out);

    // --- graph readout + classifier ---
    graph_rep_kernel<<<(B_ * (2 * DOUT_ + D_) + T - 1) / T, T>>>(concat_cls);
    init_bias_kernel<<<(B_ * LH_ + T - 1) / T, T>>>(p_hid, lin1_b, B_, LH_);
    sgemm_acc<<<gemm_grid_f32(B_, LH_), 256>>>(p_rep, lin1_w, p_hid, B_, LH_, 2 * DOUT_ + D_);
    relu_kernel<<<(B_ * LH_ + T - 1) / T, T>>>(p_hid, (long long)B_ * LH_);
    final_kernel<<<B_, 128>>>(lin2_w, lin2_b, out);
}